// round 15
// baseline (speedup 1.0000x reference)
#include <cuda_runtime.h>
#include <cuda_bf16.h>
#include <math.h>
#include <cstdint>

#define N_      16
#define C_      128
#define T_      16384
#define K_      64
#define KG_     73
#define TT_     128
#define TILES_  (T_ / TT_)   // 128
#define SL_     18           // 16*18 = 288 CTAs = 2/SM, one wave
#define EPSF    1e-12f

__device__ uint32_t g_vlad_ph[SL_ * N_ * K_ * (C_ / 2)];   // bf16x2 partials, 4.7 MB
__device__ float g_asum_part[SL_ * N_ * K_];
__device__ float g_knorm[N_ * K_];

// ---- smem layout (bytes), ~74 KB -> 2 CTAs/SM ----
#define XS_     0        // x [c=128][t=128] bf16, 256B rows, swizzled
#define W_      32768    // W [k=80][c=128] bf16, 256B rows (rows 73..79 zero)
#define SF_     53248    // soft [t=128][k=64] bf16, 128B rows, swizzled
#define NRMP    69632    // float [8][128]
#define ASW     73728    // float [8][64]
#define SMEM_SZ 75776

__device__ __forceinline__ void ldsm4(uint32_t a, uint32_t r[4]) {
    asm volatile("ldmatrix.sync.aligned.m8n8.x4.shared.b16 {%0,%1,%2,%3}, [%4];"
        : "=r"(r[0]), "=r"(r[1]), "=r"(r[2]), "=r"(r[3]) : "r"(a));
}
__device__ __forceinline__ void ldsm4t(uint32_t a, uint32_t r[4]) {
    asm volatile("ldmatrix.sync.aligned.m8n8.x4.trans.shared.b16 {%0,%1,%2,%3}, [%4];"
        : "=r"(r[0]), "=r"(r[1]), "=r"(r[2]), "=r"(r[3]) : "r"(a));
}
__device__ __forceinline__ void mma16816(float d[4], const uint32_t a[4], const uint32_t b[2]) {
    asm volatile("mma.sync.aligned.m16n8k16.row.col.f32.bf16.bf16.f32 "
        "{%0,%1,%2,%3}, {%4,%5,%6,%7}, {%8,%9}, {%0,%1,%2,%3};"
        : "+f"(d[0]), "+f"(d[1]), "+f"(d[2]), "+f"(d[3])
        : "r"(a[0]), "r"(a[1]), "r"(a[2]), "r"(a[3]), "r"(b[0]), "r"(b[1]));
}
__device__ __forceinline__ uint32_t ldsm_addr(uint32_t base, int row0, int colb0, int rs, int lane) {
    int g = lane >> 3, r = lane & 7;
    int row  = row0 + r + ((g & 2) << 2);
    int colb = colb0 + ((g & 1) << 4);
    return base + row * rs + (colb ^ ((row & 7) << 4));
}
__device__ __forceinline__ uint32_t pack2(float z0, float z1) {
    uint32_t h;
    asm("cvt.rn.bf16x2.f32 %0, %2, %1;" : "=r"(h) : "f"(z0), "f"(z1));
    return h;
}
__device__ __forceinline__ float2 unpack2(uint32_t h) {
    float2 r;
    r.x = __uint_as_float(h << 16);
    r.y = __uint_as_float(h & 0xFFFF0000u);
    return r;
}
__device__ __forceinline__ float ex2(float a) {
    float r;
    asm("ex2.approx.f32 %0, %1;" : "=f"(r) : "f"(a));
    return r;
}
__device__ __forceinline__ float2 ffma2(float2 a, float2 b, float2 c) {
    float2 d;
    asm("fma.rn.f32x2 %0, %1, %2, %3;"
        : "=l"(*(unsigned long long*)&d)
        : "l"(*(unsigned long long*)&a),
          "l"(*(unsigned long long*)&b),
          "l"(*(unsigned long long*)&c));
    return d;
}

__global__ __launch_bounds__(256, 2)
void vlad_mma(const float* __restrict__ x, const float* __restrict__ conv_w) {
    extern __shared__ __align__(16) char smem[];
    uint32_t sb;
    asm("{ .reg .u64 t; cvta.to.shared.u64 t, %1; cvt.u32.u64 %0, t; }" : "=r"(sb) : "l"(smem));

    const int n = blockIdx.x, sl = blockIdx.y;
    const int tid = threadIdx.x, w = tid >> 5, lane = tid & 31;
    const int q = lane >> 2, qk = lane & 3;

    float* nrmp = (float*)(smem + NRMP);
    float* asw  = (float*)(smem + ASW);

    // ---- W -> smem bf16, swizzled [k=80][c=128], rows >= 73 zero ----
    for (int idx = tid; idx < 80 * 128; idx += 256) {
        int k = idx >> 7, c = idx & 127;
        float v = (k < KG_) ? conv_w[k * 128 + c] : 0.f;
        int phys = k * 256 + ((c * 2) ^ ((k & 7) << 4));
        *(__nv_bfloat16*)(smem + W_ + phys) = __float2bfloat16(v);
    }

    float acc2[8][4];
#pragma unroll
    for (int i = 0; i < 8; ++i)
#pragma unroll
        for (int j = 0; j < 4; ++j) acc2[i][j] = 0.f;
    float asum_[8][2];
#pragma unroll
    for (int i = 0; i < 8; ++i) { asum_[i][0] = 0.f; asum_[i][1] = 0.f; }

    const float* xb = x + (long)n * C_ * T_;
    const int mcol1 = 32 * w;           // GEMM1 A col byte (t-block = 16w)
    const int mcol2 = 32 * (w >> 1);    // GEMM2 A col byte (k-block)
    const int nh2   = 64 * (w & 1);     // GEMM2 c-half
    const int tA    = 16 * w + q, tB = tA + 8;

    for (int tile = sl; tile < TILES_; tile += SL_) {
        __syncthreads();   // B1: XS/SF/nrmp free (prev GEMM1/2 done)
        const int t0g = tile * TT_;

        // ---- load: single 16-deep LDG burst (MLP=16), then convert + norms ----
        {
            float4 vv[16];
#pragma unroll
            for (int ci = 0; ci < 16; ++ci) {
                int c = 16 * w + ci;
                vv[ci] = *(const float4*)(xb + (long)c * T_ + t0g + 4 * lane);
            }
            float2 sqA = make_float2(0.f, 0.f), sqB = make_float2(0.f, 0.f);
#pragma unroll
            for (int ci = 0; ci < 16; ++ci) {
                int c = 16 * w + ci;
                float4 v = vv[ci];
                float2 p0 = make_float2(v.x, v.y), p1 = make_float2(v.z, v.w);
                sqA = ffma2(p0, p0, sqA);
                sqB = ffma2(p1, p1, sqB);
                int phys = c * 256 + ((8 * lane) ^ ((c & 7) << 4));
                *(uint2*)(smem + XS_ + phys) = make_uint2(pack2(v.x, v.y), pack2(v.z, v.w));
            }
            *(float4*)(nrmp + w * 128 + 4 * lane) = make_float4(sqA.x, sqA.y, sqB.x, sqB.y);
        }
        __syncthreads();   // B2: XS + nrmp ready

        // ---- GEMM1: lg[t][k] (warp owns t 16w..16w+15, all 80 k) ----
        float acc1[10][4];
#pragma unroll
        for (int i = 0; i < 10; ++i)
#pragma unroll
            for (int j = 0; j < 4; ++j) acc1[i][j] = 0.f;

#pragma unroll
        for (int kk = 0; kk < 8; ++kk) {
            uint32_t ah[4];
            ldsm4t(ldsm_addr(sb + XS_, 16 * kk, mcol1, 256, lane), ah);
#pragma unroll
            for (int np = 0; np < 5; ++np) {
                uint32_t bh[4];
                ldsm4(ldsm_addr(sb + W_, 16 * np, 32 * kk, 256, lane), bh);
                mma16816(acc1[2 * np],     ah, bh);
                mma16816(acc1[2 * np + 1], ah, bh + 2);
            }
        }

        // ---- per-thread ninv from nrmp ----
        float ssA = 0.f, ssB = 0.f;
#pragma unroll
        for (int ww = 0; ww < 8; ++ww) { ssA += nrmp[ww * 128 + tA]; ssB += nrmp[ww * 128 + tB]; }
        const float ninvA = 1.f / fmaxf(sqrtf(ssA), EPSF);
        const float ninvB = 1.f / fmaxf(sqrtf(ssB), EPSF);

        // ---- softmax, no max subtraction (args = w·x_hat ~ N(0,1), safe range) ----
        {
            const float eA = ninvA * 1.44269504f;   // ninv * log2(e)
            const float eB = ninvB * 1.44269504f;
            float sA = 0.f, sB = 0.f;
#pragma unroll
            for (int nn = 0; nn < 9; ++nn) {
                acc1[nn][0] = ex2(acc1[nn][0] * eA); sA += acc1[nn][0];
                acc1[nn][1] = ex2(acc1[nn][1] * eA); sA += acc1[nn][1];
                acc1[nn][2] = ex2(acc1[nn][2] * eB); sB += acc1[nn][2];
                acc1[nn][3] = ex2(acc1[nn][3] * eB); sB += acc1[nn][3];
            }
            if (qk == 0) {
                sA += ex2(acc1[9][0] * eA);
                sB += ex2(acc1[9][2] * eB);
            }
            sA += __shfl_xor_sync(~0u, sA, 1); sA += __shfl_xor_sync(~0u, sA, 2);
            sB += __shfl_xor_sync(~0u, sB, 1); sB += __shfl_xor_sync(~0u, sB, 2);
            const float isA = 1.f / sA, isB = 1.f / sB;

            const int swA = (tA & 7) << 4, swB = (tB & 7) << 4;
#pragma unroll
            for (int nn = 0; nn < 8; ++nn) {
                float s0 = acc1[nn][0] * isA, s1 = acc1[nn][1] * isA;
                float s2 = acc1[nn][2] * isB, s3 = acc1[nn][3] * isB;
                asum_[nn][0] += s0 + s2;
                asum_[nn][1] += s1 + s3;
                int cbyte = 16 * nn + 4 * qk;
                *(uint32_t*)(smem + SF_ + tA * 128 + (cbyte ^ swA)) = pack2(s0 * ninvA, s1 * ninvA);
                *(uint32_t*)(smem + SF_ + tB * 128 + (cbyte ^ swB)) = pack2(s2 * ninvB, s3 * ninvB);
            }
        }
        __syncthreads();   // B3: SF ready

        // ---- GEMM2: vlad[k][c] += soft_scaled[k][t] x[c][t]; warp = (k16, c64) ----
#pragma unroll
        for (int kk = 0; kk < 8; ++kk) {
            uint32_t ah[4];
            ldsm4t(ldsm_addr(sb + SF_, 16 * kk, mcol2, 128, lane), ah);
#pragma unroll
            for (int np = 0; np < 4; ++np) {
                uint32_t bh[4];
                ldsm4(ldsm_addr(sb + XS_, nh2 + 16 * np, 32 * kk, 256, lane), bh);
                mma16816(acc2[2 * np],     ah, bh);
                mma16816(acc2[2 * np + 1], ah, bh + 2);
            }
        }
    }

    // ---- asum reduce ----
    __syncthreads();
#pragma unroll
    for (int nn = 0; nn < 8; ++nn) {
#pragma unroll
        for (int e = 0; e < 2; ++e) {
            float v = asum_[nn][e];
            v += __shfl_xor_sync(~0u, v, 4);
            v += __shfl_xor_sync(~0u, v, 8);
            v += __shfl_xor_sync(~0u, v, 16);
            if (lane < 4) asw[w * 64 + 8 * nn + 2 * lane + e] = v;
        }
    }
    __syncthreads();
    if (tid < 64) {
        float s = 0.f;
#pragma unroll
        for (int ww = 0; ww < 8; ++ww) s += asw[ww * 64 + tid];
        g_asum_part[((long)(sl * N_ + n)) * K_ + tid] = s;
    }

    // ---- drain acc2 as bf16x2 pairs ----
    {
        const int kA = 16 * (w >> 1) + q, kB = kA + 8;
        uint32_t* gp = g_vlad_ph + ((long)(sl * N_ + n)) * K_ * (C_ / 2);
#pragma unroll
        for (int nn = 0; nn < 8; ++nn) {
            int c2 = (nh2 >> 1) + 4 * nn + qk;
            gp[kA * (C_ / 2) + c2] = pack2(acc2[nn][0], acc2[nn][1]);
            gp[kB * (C_ / 2) + c2] = pack2(acc2[nn][2], acc2[nn][3]);
        }
    }
}

// ---- Reduce: one CTA (64 threads) per (n,k); thread owns channel pair ----
__global__ __launch_bounds__(64)
void vlad_reduce(const float* __restrict__ centroids,
                 const float* __restrict__ cwts,
                 float* __restrict__ out) {
    const int k = blockIdx.x, n = blockIdx.y;
    const int tid = threadIdx.x, w = tid >> 5, lane = tid & 31;

    __shared__ float s_asum, s_scw, wred[2];

    float2 v = make_float2(0.f, 0.f);
    const uint32_t* base = g_vlad_ph + (long)n * K_ * (C_ / 2) + (long)k * (C_ / 2) + tid;
    const long str = (long)N_ * K_ * (C_ / 2);
#pragma unroll
    for (int sl = 0; sl < SL_; ++sl) {
        float2 p = unpack2(base[sl * str]);
        v.x += p.x; v.y += p.y;
    }

    if (w == 0) {
        float a = (lane < SL_) ? g_asum_part[((long)(lane * N_ + n)) * K_ + k] : 0.f;
        a += __shfl_xor_sync(~0u, a, 16);
        a += __shfl_xor_sync(~0u, a, 8);
        a += __shfl_xor_sync(~0u, a, 4);
        a += __shfl_xor_sync(~0u, a, 2);
        a += __shfl_xor_sync(~0u, a, 1);
        if (lane == 0) s_asum = a;
    } else {
        float c0 = cwts[lane], c1 = cwts[32 + lane];
        float s = c0 * c0 + c1 * c1;
        s += __shfl_xor_sync(~0u, s, 16);
        s += __shfl_xor_sync(~0u, s, 8);
        s += __shfl_xor_sync(~0u, s, 4);
        s += __shfl_xor_sync(~0u, s, 2);
        s += __shfl_xor_sync(~0u, s, 1);
        if (lane == 0) s_scw = 1.f / fmaxf(sqrtf(s), EPSF);
    }
    __syncthreads();

    const float2 ce = *(const float2*)(centroids + k * C_ + 2 * tid);
    v.x -= s_asum * ce.x;
    v.y -= s_asum * ce.y;

    float sq = v.x * v.x + v.y * v.y;
    sq += __shfl_xor_sync(~0u, sq, 16);
    sq += __shfl_xor_sync(~0u, sq, 8);
    sq += __shfl_xor_sync(~0u, sq, 4);
    sq += __shfl_xor_sync(~0u, sq, 2);
    sq += __shfl_xor_sync(~0u, sq, 1);
    if (lane == 0) wred[w] = sq;
    __syncthreads();
    const float ssq = wred[0] + wred[1];

    const float scale = (1.f / fmaxf(sqrtf(ssq), EPSF)) * cwts[k] * s_scw;
    *(float2*)(out + (long)n * K_ * C_ + (long)k * C_ + 2 * tid) =
        make_float2(v.x * scale, v.y * scale);
    if (tid == 0) g_knorm[n * K_ + k] = ssq * scale * scale;
}

// ---- Finalize: grid (16, 8) ----
__global__ __launch_bounds__(256)
void vlad_finalize(float* __restrict__ out) {
    const int n = blockIdx.x, part = blockIdx.y;
    const int tid = threadIdx.x, lane = tid & 31;
    __shared__ float sginv;
    if (tid < 32) {
        float g = g_knorm[n * K_ + lane] + g_knorm[n * K_ + 32 + lane];
        g += __shfl_xor_sync(~0u, g, 16);
        g += __shfl_xor_sync(~0u, g, 8);
        g += __shfl_xor_sync(~0u, g, 4);
        g += __shfl_xor_sync(~0u, g, 2);
        g += __shfl_xor_sync(~0u, g, 1);
        if (lane == 0) sginv = 1.f / fmaxf(sqrtf(g), EPSF);
    }
    __syncthreads();
    const float gi = sginv;
    float4* p = (float4*)(out + (long)n * K_ * C_) + part * 256;
    float4 v = p[tid];
    v.x *= gi; v.y *= gi; v.z *= gi; v.w *= gi;
    p[tid] = v;
}

extern "C" void kernel_launch(void* const* d_in, const int* in_sizes, int n_in,
                              void* d_out, int out_size) {
    const float* x      = (const float*)d_in[0];
    const float* conv_w = (const float*)d_in[1];
    const float* cent   = (const float*)d_in[2];
    const float* cwts   = (const float*)d_in[3];
    float* out = (float*)d_out;

    cudaFuncSetAttribute(vlad_mma, cudaFuncAttributeMaxDynamicSharedMemorySize, SMEM_SZ);
    vlad_mma<<<dim3(N_, SL_), 256, SMEM_SZ>>>(x, conv_w);
    vlad_reduce<<<dim3(K_, N_), 64>>>(cent, cwts, out);
    vlad_finalize<<<dim3(N_, 8), 256>>>(out);
}

// round 16
// speedup vs baseline: 1.0430x; 1.0430x over previous
#include <cuda_runtime.h>
#include <cuda_bf16.h>
#include <math.h>
#include <cstdint>

#define N_      16
#define C_      128
#define T_      16384
#define K_      64
#define KG_     73
#define TT_     128
#define TILES_  (T_ / TT_)   // 128
#define SL_     19           // 16*19 = 304 CTAs; every CTA <= 7 tiles (balanced)
#define EPSF    1e-12f

__device__ uint32_t g_vlad_ph[SL_ * N_ * K_ * (C_ / 2)];   // bf16x2 partials, ~5 MB
__device__ float g_asum_part[SL_ * N_ * K_];
__device__ float g_knorm[N_ * K_];

// ---- smem layout (bytes), ~74 KB -> 2 CTAs/SM ----
#define XS_     0        // x [c=128][t=128] bf16, 256B rows, swizzled
#define W_      32768    // W [k=80][c=128] bf16, 256B rows (rows 73..79 zero)
#define SF_     53248    // soft [t=128][k=64] bf16, 128B rows, swizzled
#define NRMP    69632    // float [8][128]
#define ASW     73728    // float [8][64]
#define SMEM_SZ 75776

__device__ __forceinline__ void ldsm4(uint32_t a, uint32_t r[4]) {
    asm volatile("ldmatrix.sync.aligned.m8n8.x4.shared.b16 {%0,%1,%2,%3}, [%4];"
        : "=r"(r[0]), "=r"(r[1]), "=r"(r[2]), "=r"(r[3]) : "r"(a));
}
__device__ __forceinline__ void ldsm4t(uint32_t a, uint32_t r[4]) {
    asm volatile("ldmatrix.sync.aligned.m8n8.x4.trans.shared.b16 {%0,%1,%2,%3}, [%4];"
        : "=r"(r[0]), "=r"(r[1]), "=r"(r[2]), "=r"(r[3]) : "r"(a));
}
__device__ __forceinline__ void mma16816(float d[4], const uint32_t a[4], const uint32_t b[2]) {
    asm volatile("mma.sync.aligned.m16n8k16.row.col.f32.bf16.bf16.f32 "
        "{%0,%1,%2,%3}, {%4,%5,%6,%7}, {%8,%9}, {%0,%1,%2,%3};"
        : "+f"(d[0]), "+f"(d[1]), "+f"(d[2]), "+f"(d[3])
        : "r"(a[0]), "r"(a[1]), "r"(a[2]), "r"(a[3]), "r"(b[0]), "r"(b[1]));
}
__device__ __forceinline__ uint32_t ldsm_addr(uint32_t base, int row0, int colb0, int rs, int lane) {
    int g = lane >> 3, r = lane & 7;
    int row  = row0 + r + ((g & 2) << 2);
    int colb = colb0 + ((g & 1) << 4);
    return base + row * rs + (colb ^ ((row & 7) << 4));
}
__device__ __forceinline__ uint32_t pack2(float z0, float z1) {
    uint32_t h;
    asm("cvt.rn.bf16x2.f32 %0, %2, %1;" : "=r"(h) : "f"(z0), "f"(z1));
    return h;
}
__device__ __forceinline__ float2 unpack2(uint32_t h) {
    float2 r;
    r.x = __uint_as_float(h << 16);
    r.y = __uint_as_float(h & 0xFFFF0000u);
    return r;
}
__device__ __forceinline__ float ex2(float a) {
    float r;
    asm("ex2.approx.f32 %0, %1;" : "=f"(r) : "f"(a));
    return r;
}
__device__ __forceinline__ float2 ffma2(float2 a, float2 b, float2 c) {
    float2 d;
    asm("fma.rn.f32x2 %0, %1, %2, %3;"
        : "=l"(*(unsigned long long*)&d)
        : "l"(*(unsigned long long*)&a),
          "l"(*(unsigned long long*)&b),
          "l"(*(unsigned long long*)&c));
    return d;
}

__global__ __launch_bounds__(256, 2)
void vlad_mma(const float* __restrict__ x, const float* __restrict__ conv_w) {
    extern __shared__ __align__(16) char smem[];
    uint32_t sb;
    asm("{ .reg .u64 t; cvta.to.shared.u64 t, %1; cvt.u32.u64 %0, t; }" : "=r"(sb) : "l"(smem));

    const int n = blockIdx.x, sl = blockIdx.y;
    const int tid = threadIdx.x, w = tid >> 5, lane = tid & 31;
    const int q = lane >> 2, qk = lane & 3;

    float* nrmp = (float*)(smem + NRMP);
    float* asw  = (float*)(smem + ASW);

    // ---- W -> smem bf16, swizzled [k=80][c=128], rows >= 73 zero ----
    for (int idx = tid; idx < 80 * 128; idx += 256) {
        int k = idx >> 7, c = idx & 127;
        float v = (k < KG_) ? conv_w[k * 128 + c] : 0.f;
        int phys = k * 256 + ((c * 2) ^ ((k & 7) << 4));
        *(__nv_bfloat16*)(smem + W_ + phys) = __float2bfloat16(v);
    }

    float acc2[8][4];
#pragma unroll
    for (int i = 0; i < 8; ++i)
#pragma unroll
        for (int j = 0; j < 4; ++j) acc2[i][j] = 0.f;
    float asum_[8][2];
#pragma unroll
    for (int i = 0; i < 8; ++i) { asum_[i][0] = 0.f; asum_[i][1] = 0.f; }

    const float* xb = x + (long)n * C_ * T_;
    const int mcol1 = 32 * w;           // GEMM1 A col byte (t-block = 16w)
    const int mcol2 = 32 * (w >> 1);    // GEMM2 A col byte (k-block)
    const int nh2   = 64 * (w & 1);     // GEMM2 c-half
    const int tA    = 16 * w + q, tB = tA + 8;

    for (int tile = sl; tile < TILES_; tile += SL_) {
        __syncthreads();   // B1: XS/SF/nrmp free (prev GEMM1/2 done)
        const int t0g = tile * TT_;

        // ---- load: single 16-deep LDG burst (MLP=16), then convert + norms ----
        {
            float4 vv[16];
#pragma unroll
            for (int ci = 0; ci < 16; ++ci) {
                int c = 16 * w + ci;
                vv[ci] = *(const float4*)(xb + (long)c * T_ + t0g + 4 * lane);
            }
            float2 sqA = make_float2(0.f, 0.f), sqB = make_float2(0.f, 0.f);
#pragma unroll
            for (int ci = 0; ci < 16; ++ci) {
                int c = 16 * w + ci;
                float4 v = vv[ci];
                float2 p0 = make_float2(v.x, v.y), p1 = make_float2(v.z, v.w);
                sqA = ffma2(p0, p0, sqA);
                sqB = ffma2(p1, p1, sqB);
                int phys = c * 256 + ((8 * lane) ^ ((c & 7) << 4));
                *(uint2*)(smem + XS_ + phys) = make_uint2(pack2(v.x, v.y), pack2(v.z, v.w));
            }
            *(float4*)(nrmp + w * 128 + 4 * lane) = make_float4(sqA.x, sqA.y, sqB.x, sqB.y);
        }
        __syncthreads();   // B2: XS + nrmp ready

        // ---- GEMM1: lg[t][k] (warp owns t 16w..16w+15, all 80 k) ----
        float acc1[10][4];
#pragma unroll
        for (int i = 0; i < 10; ++i)
#pragma unroll
            for (int j = 0; j < 4; ++j) acc1[i][j] = 0.f;

#pragma unroll
        for (int kk = 0; kk < 8; ++kk) {
            uint32_t ah[4];
            ldsm4t(ldsm_addr(sb + XS_, 16 * kk, mcol1, 256, lane), ah);
#pragma unroll
            for (int np = 0; np < 5; ++np) {
                uint32_t bh[4];
                ldsm4(ldsm_addr(sb + W_, 16 * np, 32 * kk, 256, lane), bh);
                mma16816(acc1[2 * np],     ah, bh);
                mma16816(acc1[2 * np + 1], ah, bh + 2);
            }
        }

        // ---- per-thread ninv from nrmp ----
        float ssA = 0.f, ssB = 0.f;
#pragma unroll
        for (int ww = 0; ww < 8; ++ww) { ssA += nrmp[ww * 128 + tA]; ssB += nrmp[ww * 128 + tB]; }
        const float ninvA = 1.f / fmaxf(sqrtf(ssA), EPSF);
        const float ninvB = 1.f / fmaxf(sqrtf(ssB), EPSF);

        // ---- softmax, no max subtraction (args = w·x_hat ~ N(0,1), safe range) ----
        {
            const float eA = ninvA * 1.44269504f;   // ninv * log2(e)
            const float eB = ninvB * 1.44269504f;
            float sA = 0.f, sB = 0.f;
#pragma unroll
            for (int nn = 0; nn < 9; ++nn) {
                acc1[nn][0] = ex2(acc1[nn][0] * eA); sA += acc1[nn][0];
                acc1[nn][1] = ex2(acc1[nn][1] * eA); sA += acc1[nn][1];
                acc1[nn][2] = ex2(acc1[nn][2] * eB); sB += acc1[nn][2];
                acc1[nn][3] = ex2(acc1[nn][3] * eB); sB += acc1[nn][3];
            }
            if (qk == 0) {
                sA += ex2(acc1[9][0] * eA);
                sB += ex2(acc1[9][2] * eB);
            }
            sA += __shfl_xor_sync(~0u, sA, 1); sA += __shfl_xor_sync(~0u, sA, 2);
            sB += __shfl_xor_sync(~0u, sB, 1); sB += __shfl_xor_sync(~0u, sB, 2);
            const float isA = 1.f / sA, isB = 1.f / sB;

            const int swA = (tA & 7) << 4, swB = (tB & 7) << 4;
#pragma unroll
            for (int nn = 0; nn < 8; ++nn) {
                float s0 = acc1[nn][0] * isA, s1 = acc1[nn][1] * isA;
                float s2 = acc1[nn][2] * isB, s3 = acc1[nn][3] * isB;
                asum_[nn][0] += s0 + s2;
                asum_[nn][1] += s1 + s3;
                int cbyte = 16 * nn + 4 * qk;
                *(uint32_t*)(smem + SF_ + tA * 128 + (cbyte ^ swA)) = pack2(s0 * ninvA, s1 * ninvA);
                *(uint32_t*)(smem + SF_ + tB * 128 + (cbyte ^ swB)) = pack2(s2 * ninvB, s3 * ninvB);
            }
        }
        __syncthreads();   // B3: SF ready

        // ---- GEMM2: vlad[k][c] += soft_scaled[k][t] x[c][t]; warp = (k16, c64) ----
#pragma unroll
        for (int kk = 0; kk < 8; ++kk) {
            uint32_t ah[4];
            ldsm4t(ldsm_addr(sb + SF_, 16 * kk, mcol2, 128, lane), ah);
#pragma unroll
            for (int np = 0; np < 4; ++np) {
                uint32_t bh[4];
                ldsm4(ldsm_addr(sb + XS_, nh2 + 16 * np, 32 * kk, 256, lane), bh);
                mma16816(acc2[2 * np],     ah, bh);
                mma16816(acc2[2 * np + 1], ah, bh + 2);
            }
        }
    }

    // ---- asum reduce ----
    __syncthreads();
#pragma unroll
    for (int nn = 0; nn < 8; ++nn) {
#pragma unroll
        for (int e = 0; e < 2; ++e) {
            float v = asum_[nn][e];
            v += __shfl_xor_sync(~0u, v, 4);
            v += __shfl_xor_sync(~0u, v, 8);
            v += __shfl_xor_sync(~0u, v, 16);
            if (lane < 4) asw[w * 64 + 8 * nn + 2 * lane + e] = v;
        }
    }
    __syncthreads();
    if (tid < 64) {
        float s = 0.f;
#pragma unroll
        for (int ww = 0; ww < 8; ++ww) s += asw[ww * 64 + tid];
        g_asum_part[((long)(sl * N_ + n)) * K_ + tid] = s;
    }

    // ---- drain acc2 as bf16x2 pairs ----
    {
        const int kA = 16 * (w >> 1) + q, kB = kA + 8;
        uint32_t* gp = g_vlad_ph + ((long)(sl * N_ + n)) * K_ * (C_ / 2);
#pragma unroll
        for (int nn = 0; nn < 8; ++nn) {
            int c2 = (nh2 >> 1) + 4 * nn + qk;
            gp[kA * (C_ / 2) + c2] = pack2(acc2[nn][0], acc2[nn][1]);
            gp[kB * (C_ / 2) + c2] = pack2(acc2[nn][2], acc2[nn][3]);
        }
    }
}

// ---- Reduce: one CTA (64 threads) per (n,k); thread owns channel pair ----
__global__ __launch_bounds__(64)
void vlad_reduce(const float* __restrict__ centroids,
                 const float* __restrict__ cwts,
                 float* __restrict__ out) {
    const int k = blockIdx.x, n = blockIdx.y;
    const int tid = threadIdx.x, w = tid >> 5, lane = tid & 31;

    __shared__ float s_asum, s_scw, wred[2];

    float2 v = make_float2(0.f, 0.f);
    const uint32_t* base = g_vlad_ph + (long)n * K_ * (C_ / 2) + (long)k * (C_ / 2) + tid;
    const long str = (long)N_ * K_ * (C_ / 2);
#pragma unroll
    for (int sl = 0; sl < SL_; ++sl) {
        float2 p = unpack2(base[sl * str]);
        v.x += p.x; v.y += p.y;
    }

    if (w == 0) {
        float a = (lane < SL_) ? g_asum_part[((long)(lane * N_ + n)) * K_ + k] : 0.f;
        a += __shfl_xor_sync(~0u, a, 16);
        a += __shfl_xor_sync(~0u, a, 8);
        a += __shfl_xor_sync(~0u, a, 4);
        a += __shfl_xor_sync(~0u, a, 2);
        a += __shfl_xor_sync(~0u, a, 1);
        if (lane == 0) s_asum = a;
    } else {
        float c0 = cwts[lane], c1 = cwts[32 + lane];
        float s = c0 * c0 + c1 * c1;
        s += __shfl_xor_sync(~0u, s, 16);
        s += __shfl_xor_sync(~0u, s, 8);
        s += __shfl_xor_sync(~0u, s, 4);
        s += __shfl_xor_sync(~0u, s, 2);
        s += __shfl_xor_sync(~0u, s, 1);
        if (lane == 0) s_scw = 1.f / fmaxf(sqrtf(s), EPSF);
    }
    __syncthreads();

    const float2 ce = *(const float2*)(centroids + k * C_ + 2 * tid);
    v.x -= s_asum * ce.x;
    v.y -= s_asum * ce.y;

    float sq = v.x * v.x + v.y * v.y;
    sq += __shfl_xor_sync(~0u, sq, 16);
    sq += __shfl_xor_sync(~0u, sq, 8);
    sq += __shfl_xor_sync(~0u, sq, 4);
    sq += __shfl_xor_sync(~0u, sq, 2);
    sq += __shfl_xor_sync(~0u, sq, 1);
    if (lane == 0) wred[w] = sq;
    __syncthreads();
    const float ssq = wred[0] + wred[1];

    const float scale = (1.f / fmaxf(sqrtf(ssq), EPSF)) * cwts[k] * s_scw;
    *(float2*)(out + (long)n * K_ * C_ + (long)k * C_ + 2 * tid) =
        make_float2(v.x * scale, v.y * scale);
    if (tid == 0) g_knorm[n * K_ + k] = ssq * scale * scale;
}

// ---- Finalize: grid (16, 8) ----
__global__ __launch_bounds__(256)
void vlad_finalize(float* __restrict__ out) {
    const int n = blockIdx.x, part = blockIdx.y;
    const int tid = threadIdx.x, lane = tid & 31;
    __shared__ float sginv;
    if (tid < 32) {
        float g = g_knorm[n * K_ + lane] + g_knorm[n * K_ + 32 + lane];
        g += __shfl_xor_sync(~0u, g, 16);
        g += __shfl_xor_sync(~0u, g, 8);
        g += __shfl_xor_sync(~0u, g, 4);
        g += __shfl_xor_sync(~0u, g, 2);
        g += __shfl_xor_sync(~0u, g, 1);
        if (lane == 0) sginv = 1.f / fmaxf(sqrtf(g), EPSF);
    }
    __syncthreads();
    const float gi = sginv;
    float4* p = (float4*)(out + (long)n * K_ * C_) + part * 256;
    float4 v = p[tid];
    v.x *= gi; v.y *= gi; v.z *= gi; v.w *= gi;
    p[tid] = v;
}

extern "C" void kernel_launch(void* const* d_in, const int* in_sizes, int n_in,
                              void* d_out, int out_size) {
    const float* x      = (const float*)d_in[0];
    const float* conv_w = (const float*)d_in[1];
    const float* cent   = (const float*)d_in[2];
    const float* cwts   = (const float*)d_in[3];
    float* out = (float*)d_out;

    cudaFuncSetAttribute(vlad_mma, cudaFuncAttributeMaxDynamicSharedMemorySize, SMEM_SZ);
    vlad_mma<<<dim3(N_, SL_), 256, SMEM_SZ>>>(x, conv_w);
    vlad_reduce<<<dim3(K_, N_), 64>>>(cent, cwts, out);
    vlad_finalize<<<dim3(N_, 8), 256>>>(out);
}